// round 1
// baseline (speedup 1.0000x reference)
#include <cuda_runtime.h>
#include <math.h>

// Problem constants
#define B_      2
#define S_      2048
#define DMODEL  2048
#define NH      16
#define DH      128
#define DLAT    512
#define DR      64
#define DQK     192            // DH + DR
#define KVD     320            // DH + DR + DH
#define QFD     3072           // NH * DQK
#define KVFD    5120           // NH * KVD
#define ROWS    (B_*S_)        // 4096

// Scratch (device globals: allocation-free contract)
__device__ float g_kvlat[(size_t)ROWS * DLAT];
__device__ float g_qlat [(size_t)ROWS * DLAT];
__device__ float g_kvfull[(size_t)ROWS * KVFD];
__device__ float g_qfull [(size_t)ROWS * QFD];
__device__ float g_ctx   [(size_t)ROWS * DMODEL];

// ---------------------------------------------------------------------------
// SGEMM: C[M,N] = A[M,K] @ B[K,N], row-major, fp32.
// BM=BN=128, BK=8, 256 threads, 8x8 microtile (4+4 split for conflict-free smem).
// Requires M%128==0, N%128==0, K%8==0 (true for all our shapes).
// ---------------------------------------------------------------------------
__global__ __launch_bounds__(256) void sgemm_kernel(
    const float* __restrict__ A, const float* __restrict__ Bm,
    float* __restrict__ C, int M, int N, int K)
{
    __shared__ float As[8][128];
    __shared__ float Bs[8][128];

    const int tid = threadIdx.x;
    const int bx = blockIdx.x, by = blockIdx.y;
    const int ty = tid >> 4, tx = tid & 15;

    const float* Ablk = A + (size_t)by * 128 * K;
    const float* Bblk = Bm + (size_t)bx * 128;

    float acc[8][8];
#pragma unroll
    for (int i = 0; i < 8; i++)
#pragma unroll
        for (int j = 0; j < 8; j++) acc[i][j] = 0.f;

    const int arow = tid >> 1;         // 0..127
    const int ac4  = (tid & 1) * 4;    // 0 or 4
    const int brow = tid >> 5;         // 0..7
    const int bc4  = (tid & 31) * 4;   // 0..124

    for (int k0 = 0; k0 < K; k0 += 8) {
        // stage next tile through registers (global loads issue pre-sync)
        float4 av = *(const float4*)&Ablk[(size_t)arow * K + k0 + ac4];
        float4 bv = *(const float4*)&Bblk[(size_t)(k0 + brow) * N + bc4];
        __syncthreads();
        As[ac4 + 0][arow] = av.x;
        As[ac4 + 1][arow] = av.y;
        As[ac4 + 2][arow] = av.z;
        As[ac4 + 3][arow] = av.w;
        *(float4*)&Bs[brow][bc4] = bv;
        __syncthreads();

#pragma unroll
        for (int k = 0; k < 8; k++) {
            float4 a0 = *(const float4*)&As[k][ty * 4];
            float4 a1 = *(const float4*)&As[k][64 + ty * 4];
            float4 b0 = *(const float4*)&Bs[k][tx * 4];
            float4 b1 = *(const float4*)&Bs[k][64 + tx * 4];
            float ar[8] = {a0.x, a0.y, a0.z, a0.w, a1.x, a1.y, a1.z, a1.w};
            float br[8] = {b0.x, b0.y, b0.z, b0.w, b1.x, b1.y, b1.z, b1.w};
#pragma unroll
            for (int i = 0; i < 8; i++)
#pragma unroll
                for (int j = 0; j < 8; j++)
                    acc[i][j] += ar[i] * br[j];
        }
    }

#pragma unroll
    for (int i = 0; i < 8; i++) {
        int row = by * 128 + ((i < 4) ? (ty * 4 + i) : (64 + ty * 4 + i - 4));
        float4 c0 = make_float4(acc[i][0], acc[i][1], acc[i][2], acc[i][3]);
        float4 c1 = make_float4(acc[i][4], acc[i][5], acc[i][6], acc[i][7]);
        *(float4*)&C[(size_t)row * N + bx * 128 + tx * 4]      = c0;
        *(float4*)&C[(size_t)row * N + bx * 128 + 64 + tx * 4] = c1;
    }
}

// ---------------------------------------------------------------------------
// RoPE (in-place on q_full and kv_full rope slices).
// grid = ROWS, block = 512 (16 heads x 32 pair-lanes)
// out[j]    = x[j]*cos - x[j+32]*sin
// out[j+32] = x[j+32]*cos + x[j]*sin     (cos/sin share inv_freq[j])
// ---------------------------------------------------------------------------
__global__ __launch_bounds__(512) void rope_kernel()
{
    const int row = blockIdx.x;         // b*S + s
    const int s   = row & (S_ - 1);
    const int h   = threadIdx.x >> 5;
    const int j   = threadIdx.x & 31;

    // inv_freq = 10000^(-j/32)
    const float inv = expf(-(float)j * (9.210340371976184f / 32.f));
    const float f   = (float)s * inv;
    const float c   = cosf(f);
    const float sn  = sinf(f);

    {
        size_t base = (size_t)row * QFD + h * DQK + DH;
        float x1 = g_qfull[base + j];
        float x2 = g_qfull[base + 32 + j];
        g_qfull[base + j]      = x1 * c - x2 * sn;
        g_qfull[base + 32 + j] = x2 * c + x1 * sn;
    }
    {
        size_t base = (size_t)row * KVFD + h * KVD + DH;
        float x1 = g_kvfull[base + j];
        float x2 = g_kvfull[base + 32 + j];
        g_kvfull[base + j]      = x1 * c - x2 * sn;
        g_kvfull[base + 32 + j] = x2 * c + x1 * sn;
    }
}

// ---------------------------------------------------------------------------
// Flash attention (causal): grid (S/64, NH, B), 256 threads.
// BM=BN=64. Q scaled on load. Online softmax, one expf per score element.
// ---------------------------------------------------------------------------
#define BM 64
#define BN 64
#define QS_STRIDE 196          // 192 padded (stride mod 32 == 4 -> conflict free)
#define KS_STRIDE 196
#define SS_STRIDE 68           // 64 padded
#define ATTN_SMEM_FLOATS (BM*QS_STRIDE + BN*KS_STRIDE + BN*DH + BM*SS_STRIDE + 2*BM)
#define ATTN_SMEM_BYTES  (ATTN_SMEM_FLOATS * 4)

__global__ __launch_bounds__(256) void attn_kernel()
{
    extern __shared__ float sm[];
    float* Qs   = sm;
    float* Ks   = Qs + BM * QS_STRIDE;
    float* Vs   = Ks + BN * KS_STRIDE;
    float* Ss   = Vs + BN * DH;
    float* sm_m = Ss + BM * SS_STRIDE;
    float* sm_l = sm_m + BM;

    const int qt  = blockIdx.x;
    const int h   = blockIdx.y;
    const int b   = blockIdx.z;
    const int tid = threadIdx.x;
    const int qs0 = qt * BM;

    const int ty = tid >> 4, tx = tid & 15;      // score mapping: rows ty*4.., cols tx*4..
    const int rpv = tid >> 2, cpv = tid & 3;     // PV mapping: row rpv, col chunks cpv+4*uu

    const float scale = 0.07216878364870323f;    // 1/sqrt(192)

    // Load Q tile (scaled)
    for (int f = tid; f < BM * 48; f += 256) {
        int r = f / 48, v = f % 48;
        float4 q = *(const float4*)&g_qfull[(size_t)(b * S_ + qs0 + r) * QFD + h * DQK + v * 4];
        q.x *= scale; q.y *= scale; q.z *= scale; q.w *= scale;
        *(float4*)&Qs[r * QS_STRIDE + v * 4] = q;
    }

    float m_run = -1e30f, l_run = 0.f;
    float4 o[8];
#pragma unroll
    for (int u = 0; u < 8; u++) o[u] = make_float4(0.f, 0.f, 0.f, 0.f);

    __syncthreads();

    for (int kt = 0; kt <= qs0; kt += BN) {
        // Load K (192 dims) + V (128 dims) for 64 rows
        for (int f = tid; f < BN * 80; f += 256) {
            int r = f / 80, v = f % 80;
            float4 t = *(const float4*)&g_kvfull[(size_t)(b * S_ + kt + r) * KVFD + h * KVD + v * 4];
            if (v < 48) *(float4*)&Ks[r * KS_STRIDE + v * 4] = t;
            else        *(float4*)&Vs[r * DH + (v - 48) * 4] = t;
        }
        __syncthreads();

        // Scores: 4x4 microtile per thread
        float s[4][4];
#pragma unroll
        for (int i = 0; i < 4; i++)
#pragma unroll
            for (int j = 0; j < 4; j++) s[i][j] = 0.f;

#pragma unroll 4
        for (int k = 0; k < DQK; k += 4) {
            float4 qv[4], kv[4];
#pragma unroll
            for (int i = 0; i < 4; i++) qv[i] = *(const float4*)&Qs[(ty * 4 + i) * QS_STRIDE + k];
#pragma unroll
            for (int j = 0; j < 4; j++) kv[j] = *(const float4*)&Ks[(tx * 4 + j) * KS_STRIDE + k];
#pragma unroll
            for (int i = 0; i < 4; i++)
#pragma unroll
                for (int j = 0; j < 4; j++)
                    s[i][j] += qv[i].x * kv[j].x + qv[i].y * kv[j].y
                             + qv[i].z * kv[j].z + qv[i].w * kv[j].w;
        }

        if (kt == qs0) {  // diagonal tile: causal mask
#pragma unroll
            for (int i = 0; i < 4; i++)
#pragma unroll
                for (int j = 0; j < 4; j++)
                    if (tx * 4 + j > ty * 4 + i) s[i][j] = -1e30f;
        }

        // Row max via shfl across the 16 tx lanes sharing a ty
        float rm[4];
#pragma unroll
        for (int i = 0; i < 4; i++) {
            float m = fmaxf(fmaxf(s[i][0], s[i][1]), fmaxf(s[i][2], s[i][3]));
#pragma unroll
            for (int off = 8; off >= 1; off >>= 1)
                m = fmaxf(m, __shfl_xor_sync(0xffffffffu, m, off));
            rm[i] = m;
            if (tx == 0) sm_m[ty * 4 + i] = m;
        }
        __syncthreads();

        // Exp + row sum; store p into Ss
#pragma unroll
        for (int i = 0; i < 4; i++) {
            float m = rm[i];
            float4 p;
            p.x = __expf(s[i][0] - m);
            p.y = __expf(s[i][1] - m);
            p.z = __expf(s[i][2] - m);
            p.w = __expf(s[i][3] - m);
            *(float4*)&Ss[(ty * 4 + i) * SS_STRIDE + tx * 4] = p;
            float rs = p.x + p.y + p.z + p.w;
#pragma unroll
            for (int off = 8; off >= 1; off >>= 1)
                rs += __shfl_xor_sync(0xffffffffu, rs, off);
            if (tx == 0) sm_l[ty * 4 + i] = rs;
        }
        __syncthreads();

        // Online update + P@V
        {
            float mt = sm_m[rpv], lt = sm_l[rpv];
            float m_new = fmaxf(m_run, mt);
            float corr  = __expf(m_run - m_new);
            float fac   = __expf(mt - m_new);
            l_run = l_run * corr + lt * fac;
            m_run = m_new;
#pragma unroll
            for (int u = 0; u < 8; u++) {
                o[u].x *= corr; o[u].y *= corr; o[u].z *= corr; o[u].w *= corr;
            }
#pragma unroll 4
            for (int j = 0; j < BN; j++) {
                float p = Ss[rpv * SS_STRIDE + j] * fac;
#pragma unroll
                for (int u = 0; u < 8; u++) {
                    float4 v = *(const float4*)&Vs[j * DH + (cpv + 4 * u) * 4];
                    o[u].x += p * v.x; o[u].y += p * v.y;
                    o[u].z += p * v.z; o[u].w += p * v.w;
                }
            }
        }
        __syncthreads();   // protect Ks/Vs/Ss before next tile load
    }

    // Finalize and store context (layout [b,s,h*128+d])
    float inv_l = 1.f / l_run;
#pragma unroll
    for (int u = 0; u < 8; u++) {
        float4 w = o[u];
        w.x *= inv_l; w.y *= inv_l; w.z *= inv_l; w.w *= inv_l;
        *(float4*)&g_ctx[(size_t)(b * S_ + qs0 + rpv) * DMODEL + h * DH + (cpv + 4 * u) * 4] = w;
    }
}

// ---------------------------------------------------------------------------
// Launch
// ---------------------------------------------------------------------------
extern "C" void kernel_launch(void* const* d_in, const int* in_sizes, int n_in,
                              void* d_out, int out_size)
{
    (void)in_sizes; (void)n_in; (void)out_size;
    const float* x    = (const float*)d_in[0];
    const float* Wkvd = (const float*)d_in[1];
    const float* Wkvu = (const float*)d_in[2];
    const float* Wqd  = (const float*)d_in[3];
    const float* Wqu  = (const float*)d_in[4];
    const float* Wo   = (const float*)d_in[5];
    float* out = (float*)d_out;

    float *kvlat, *qlat, *kvfull, *qfull, *ctx;
    cudaGetSymbolAddress((void**)&kvlat,  g_kvlat);
    cudaGetSymbolAddress((void**)&qlat,   g_qlat);
    cudaGetSymbolAddress((void**)&kvfull, g_kvfull);
    cudaGetSymbolAddress((void**)&qfull,  g_qfull);
    cudaGetSymbolAddress((void**)&ctx,    g_ctx);

    dim3 t(256);
    // 1) down-projections
    sgemm_kernel<<<dim3(DLAT / 128, ROWS / 128), t>>>(x, Wkvd, kvlat, ROWS, DLAT, DMODEL);
    sgemm_kernel<<<dim3(DLAT / 128, ROWS / 128), t>>>(x, Wqd,  qlat,  ROWS, DLAT, DMODEL);
    // 2) up-projections
    sgemm_kernel<<<dim3(KVFD / 128, ROWS / 128), t>>>(kvlat, Wkvu, kvfull, ROWS, KVFD, DLAT);
    sgemm_kernel<<<dim3(QFD  / 128, ROWS / 128), t>>>(qlat,  Wqu,  qfull,  ROWS, QFD,  DLAT);
    // 3) RoPE in place
    rope_kernel<<<ROWS, 512>>>();
    // 4) attention
    cudaFuncSetAttribute(attn_kernel, cudaFuncAttributeMaxDynamicSharedMemorySize, ATTN_SMEM_BYTES);
    attn_kernel<<<dim3(S_ / BM, NH, B_), 256, ATTN_SMEM_BYTES>>>();
    // 5) output projection
    sgemm_kernel<<<dim3(DMODEL / 128, ROWS / 128), t>>>(ctx, Wo, out, ROWS, DMODEL, DMODEL);
}